// round 4
// baseline (speedup 1.0000x reference)
#include <cuda_runtime.h>
#include <cuda_bf16.h>
#include <cstdint>

#define D_MODEL  1024
#define N_CTX    2049
#define B_SZ     2
#define SEQ_LEN  2048
#define M_ROWS   (B_SZ * N_CTX)   /* 4098 */
#define N_HEADS  16
#define D_K      64
#define N_LAYERS 16
#define VOCAB    256

typedef unsigned long long ull;

// ---------------- device scratch ----------------
__device__ float g_X[M_ROWS * D_MODEL];
__device__ float g_Q[M_ROWS * D_MODEL];
__device__ float g_K[M_ROWS * D_MODEL];
__device__ float g_V[M_ROWS * D_MODEL];
__device__ float g_O[M_ROWS * D_MODEL];
__device__ __nv_bfloat16 g_Xb[M_ROWS * D_MODEL];
__device__ __nv_bfloat16 g_Ob[M_ROWS * D_MODEL];
__device__ __nv_bfloat16 g_Wtq[N_LAYERS * D_MODEL * D_MODEL];
__device__ __nv_bfloat16 g_Wtk[N_LAYERS * D_MODEL * D_MODEL];
__device__ __nv_bfloat16 g_Wtv[N_LAYERS * D_MODEL * D_MODEL];
__device__ __nv_bfloat16 g_Wto[N_LAYERS * D_MODEL * D_MODEL];

// ---------------- f32x2 helpers ----------------
__device__ __forceinline__ ull pack2(float x, float y) {
    ull r; asm("mov.b64 %0, {%1, %2};" : "=l"(r) : "f"(x), "f"(y)); return r;
}
__device__ __forceinline__ void fma2(ull& d, ull a, ull b) {
    asm("fma.rn.f32x2 %0, %1, %2, %3;" : "=l"(d) : "l"(a), "l"(b), "l"(d));
}
__device__ __forceinline__ ull mul2(ull a, ull b) {
    ull r; asm("mul.rn.f32x2 %0, %1, %2;" : "=l"(r) : "l"(a), "l"(b)); return r;
}
__device__ __forceinline__ float2 unpack2(ull v) {
    float2 r; asm("mov.b64 {%0, %1}, %2;" : "=f"(r.x), "=f"(r.y) : "l"(v)); return r;
}

// ---------------- mma / ldmatrix helpers (family-common HMMA path) ----------------
__device__ __forceinline__ uint32_t smem_u32(const void* p) {
    uint32_t a;
    asm("{ .reg .u64 t; cvta.to.shared.u64 t, %1; cvt.u32.u64 %0, t; }" : "=r"(a) : "l"(p));
    return a;
}
__device__ __forceinline__ void ldm_x4(uint32_t& r0, uint32_t& r1, uint32_t& r2, uint32_t& r3,
                                       uint32_t addr) {
    asm volatile("ldmatrix.sync.aligned.m8n8.x4.shared.b16 {%0,%1,%2,%3}, [%4];"
                 : "=r"(r0), "=r"(r1), "=r"(r2), "=r"(r3) : "r"(addr));
}
__device__ __forceinline__ void mma_bf16(float* d, const uint32_t* a, const uint32_t* b) {
    asm volatile("mma.sync.aligned.m16n8k16.row.col.f32.bf16.bf16.f32 "
                 "{%0,%1,%2,%3}, {%4,%5,%6,%7}, {%8,%9}, {%0,%1,%2,%3};"
                 : "+f"(d[0]), "+f"(d[1]), "+f"(d[2]), "+f"(d[3])
                 : "r"(a[0]), "r"(a[1]), "r"(a[2]), "r"(a[3]), "r"(b[0]), "r"(b[1]));
}

// ---------------- embedding ----------------
__global__ void embed_kernel(const int* __restrict__ ids, const float* __restrict__ emb) {
    int i = blockIdx.x * blockDim.x + threadIdx.x;
    if (i >= M_ROWS * D_MODEL) return;
    int r = i >> 10;
    int d = i & 1023;
    int b = r / N_CTX;
    int t = r - b * N_CTX;
    int tok = (t == 0) ? 0 : ids[b * SEQ_LEN + (t - 1)];
    g_X[i] = emb[tok * D_MODEL + d];
}

// ---------------- weight transpose + bf16 convert: Wt[n][k] = bf16(W[k][n]) ----------------
__global__ void wtrans_kernel(const float* __restrict__ W, __nv_bfloat16* __restrict__ Wt) {
    __shared__ float t[32][33];
    const int l = blockIdx.z;
    const float* Wl = W + (size_t)l * D_MODEL * D_MODEL;
    __nv_bfloat16* Wo = Wt + (size_t)l * D_MODEL * D_MODEL;
    const int x0 = blockIdx.x * 32, y0 = blockIdx.y * 32;
    const int tx = threadIdx.x, ty = threadIdx.y;
    #pragma unroll
    for (int i = 0; i < 32; i += 8)
        t[ty + i][tx] = Wl[(size_t)(y0 + ty + i) * 1024 + x0 + tx];
    __syncthreads();
    #pragma unroll
    for (int i = 0; i < 32; i += 8)
        Wo[(size_t)(x0 + ty + i) * 1024 + y0 + tx] = __float2bfloat16_rn(t[tx][ty + i]);
}

// ---------------- fp32 -> bf16 convert ----------------
__global__ void conv_kernel(const float* __restrict__ in, __nv_bfloat16* __restrict__ out) {
    int i = blockIdx.x * blockDim.x + threadIdx.x;
    if (i >= M_ROWS * D_MODEL / 4) return;
    float4 v = ((const float4*)in)[i];
    ((__nv_bfloat162*)out)[2 * i]     = __floats2bfloat162_rn(v.x, v.y);
    ((__nv_bfloat162*)out)[2 * i + 1] = __floats2bfloat162_rn(v.z, v.w);
}

// ---------------- HMMA bf16 GEMM: C[M,1024] = A[M,1024] @ Bt[n,k]^T (+Res) ----------------
// 128x128x32 tile, 256 threads (8 warps, warp tile 32x64), double-buffered smem,
// 80B row stride (conflict-free ldmatrix), fp32 accum.
#define ROWB 40   /* bf16 per smem row (80 bytes) */
__global__ __launch_bounds__(256, 2) void gemm_bf16(const __nv_bfloat16* __restrict__ A,
                                                    const __nv_bfloat16* __restrict__ Bt,
                                                    const float* __restrict__ Res,
                                                    float* __restrict__ C) {
    __shared__ __align__(16) __nv_bfloat16 As[2][128 * ROWB];
    __shared__ __align__(16) __nv_bfloat16 Bs[2][128 * ROWB];
    const int tid = threadIdx.x;
    const int wid = tid >> 5;
    const int lane = tid & 31;
    const int wm = wid & 3;        // warp M position (0..3) -> rows wm*32
    const int wn = wid >> 2;       // warp N position (0..1) -> cols wn*64
    const int row0 = blockIdx.y * 128;
    const int col0 = blockIdx.x * 128;

    // global-load indices: 512 uint4 per tile per matrix -> 2 per thread
    const int lr0 = tid >> 1;                  // rows 0..127 (two quarters each)
    const int lq0 = (tid & 1) * 2;             // quarters 0,2
    // we do quarters lq0 and lq0+1 for row lr0
    const int agr = row0 + lr0;

    float acc[2][8][4];
    #pragma unroll
    for (int mt = 0; mt < 2; mt++)
        #pragma unroll
        for (int nt = 0; nt < 8; nt++)
            #pragma unroll
            for (int e = 0; e < 4; e++) acc[mt][nt][e] = 0.f;

    // ldmatrix smem address components (element offsets in bf16 units)
    const int aRow = wm * 32 + (lane & 15);              // + mt*16
    const int aColB = ((lane >> 4) & 1) * 8;             // +kk*16 bf16
    const int bRow = wn * 64 + (lane & 7) + ((lane >> 4) & 1) * 8;   // + g*16
    const int bColB = ((lane >> 3) & 1) * 8;

    uint32_t asb[2], bsb[2];
    asb[0] = smem_u32(As[0]); asb[1] = smem_u32(As[1]);
    bsb[0] = smem_u32(Bs[0]); bsb[1] = smem_u32(Bs[1]);

    // prefetch + store chunk 0
    uint4 ra[2], rb[2];
    {
        #pragma unroll
        for (int i = 0; i < 2; i++) {
            int q = lq0 + i;
            ra[i] = make_uint4(0u, 0u, 0u, 0u);
            if (agr < M_ROWS) ra[i] = *(const uint4*)(A + ((size_t)agr << 10) + q * 8);
            rb[i] = *(const uint4*)(Bt + ((size_t)(col0 + lr0) << 10) + q * 8);
        }
        #pragma unroll
        for (int i = 0; i < 2; i++) {
            int q = lq0 + i;
            *(uint4*)(As[0] + lr0 * ROWB + q * 8) = ra[i];
            *(uint4*)(Bs[0] + lr0 * ROWB + q * 8) = rb[i];
        }
    }
    __syncthreads();

    for (int kt = 0; kt < 32; kt++) {
        const int cur = kt & 1;
        if (kt < 31) {
            const int koff = (kt + 1) * 32;
            #pragma unroll
            for (int i = 0; i < 2; i++) {
                int q = lq0 + i;
                ra[i] = make_uint4(0u, 0u, 0u, 0u);
                if (agr < M_ROWS) ra[i] = *(const uint4*)(A + ((size_t)agr << 10) + koff + q * 8);
                rb[i] = *(const uint4*)(Bt + ((size_t)(col0 + lr0) << 10) + koff + q * 8);
            }
        }
        // compute on smem[cur]: two k16 steps
        #pragma unroll
        for (int kk = 0; kk < 2; kk++) {
            uint32_t bfr[8][2];
            #pragma unroll
            for (int g = 0; g < 4; g++) {
                uint32_t r0, r1, r2, r3;
                uint32_t addr = bsb[cur] + (uint32_t)(((bRow + g * 16) * ROWB + kk * 16 + bColB) * 2);
                ldm_x4(r0, r1, r2, r3, addr);
                bfr[2 * g][0] = r0; bfr[2 * g][1] = r1;
                bfr[2 * g + 1][0] = r2; bfr[2 * g + 1][1] = r3;
            }
            #pragma unroll
            for (int mt = 0; mt < 2; mt++) {
                uint32_t afr[4];
                uint32_t addr = asb[cur] + (uint32_t)(((aRow + mt * 16) * ROWB + kk * 16 + aColB) * 2);
                ldm_x4(afr[0], afr[1], afr[2], afr[3], addr);
                #pragma unroll
                for (int nt = 0; nt < 8; nt++)
                    mma_bf16(acc[mt][nt], afr, bfr[nt]);
            }
        }
        if (kt < 31) {
            const int nxt = cur ^ 1;
            #pragma unroll
            for (int i = 0; i < 2; i++) {
                int q = lq0 + i;
                *(uint4*)(As[nxt] + lr0 * ROWB + q * 8) = ra[i];
                *(uint4*)(Bs[nxt] + lr0 * ROWB + q * 8) = rb[i];
            }
        }
        __syncthreads();
    }

    // epilogue: fragments -> gmem (+ residual)
    #pragma unroll
    for (int mt = 0; mt < 2; mt++) {
        #pragma unroll
        for (int half = 0; half < 2; half++) {
            int gr = row0 + wm * 32 + mt * 16 + (lane >> 2) + half * 8;
            if (gr >= M_ROWS) continue;
            #pragma unroll
            for (int nt = 0; nt < 8; nt++) {
                int col = col0 + wn * 64 + nt * 8 + (lane & 3) * 2;
                float2 v = make_float2(acc[mt][nt][2 * half], acc[mt][nt][2 * half + 1]);
                size_t o = ((size_t)gr << 10) + col;
                if (Res) {
                    float2 rv = *(const float2*)(Res + o);
                    v.x += rv.x; v.y += rv.y;
                }
                *(float2*)(C + o) = v;
            }
        }
    }
}

// ---------------- causal flash attention: quad-per-query, f32x2, no spills ----------------
#define QT 64
#define KT 16
__global__ __launch_bounds__(256) void attn_kernel(const float* __restrict__ Qm,
                                                   const float* __restrict__ Km,
                                                   const float* __restrict__ Vm,
                                                   float* __restrict__ Om) {
    const int h = blockIdx.y;
    const int b = blockIdx.z;
    int q0 = blockIdx.x * QT;
    if (q0 + QT > N_CTX) q0 = N_CTX - QT;          // clamp (overlap recomputes identical rows)
    const int quad = threadIdx.x >> 2;             // 0..63 query within tile
    const int sub = threadIdx.x & 3;               // dims [sub*16, sub*16+16)
    const int q = q0 + quad;
    const unsigned qmask = 0xFu << ((threadIdx.x & 31) & ~3);
    const size_t base = (size_t)b * N_CTX * D_MODEL + (size_t)h * D_K;

    __shared__ float Ks[KT][64];
    __shared__ float Vs[KT][64];

    ull q2[8];
    {
        const ulonglong2* qp = (const ulonglong2*)(Qm + base + ((size_t)q << 10) + sub * 16);
        #pragma unroll
        for (int i = 0; i < 4; i++) { ulonglong2 t = qp[i]; q2[2 * i] = t.x; q2[2 * i + 1] = t.y; }
    }
    ull o2[8];
    #pragma unroll
    for (int i = 0; i < 8; i++) o2[i] = 0ULL;
    float mrun = -1e30f, lrun = 0.f;

    const int kmax = q0 + QT;
    for (int k0 = 0; k0 < kmax; k0 += KT) {
        __syncthreads();
        {
            int kk = threadIdx.x >> 4;
            int c4 = (threadIdx.x & 15) << 2;
            int kg = k0 + kk;
            float4 kv = make_float4(0.f, 0.f, 0.f, 0.f);
            float4 vv = make_float4(0.f, 0.f, 0.f, 0.f);
            if (kg < N_CTX) {
                kv = *(const float4*)(Km + base + ((size_t)kg << 10) + c4);
                vv = *(const float4*)(Vm + base + ((size_t)kg << 10) + c4);
            }
            *(float4*)&Ks[kk][c4] = kv;
            *(float4*)&Vs[kk][c4] = vv;
        }
        __syncthreads();
        if (q >= k0) {                              // quad-uniform branch
            float s[KT];
            float tmax = -1e30f;
            #pragma unroll
            for (int j = 0; j < KT; j++) {
                ull a0 = 0ULL, a1 = 0ULL;
                const ulonglong2* kp = (const ulonglong2*)&Ks[j][sub * 16];
                #pragma unroll
                for (int i = 0; i < 4; i++) {
                    ulonglong2 k2 = kp[i];
                    fma2(a0, q2[2 * i], k2.x);
                    fma2(a1, q2[2 * i + 1], k2.y);
                }
                float2 u0 = unpack2(a0), u1 = unpack2(a1);
                float sv = (u0.x + u0.y) + (u1.x + u1.y);
                sv += __shfl_xor_sync(qmask, sv, 1);
                sv += __shfl_xor_sync(qmask, sv, 2);
                sv = (k0 + j <= q) ? sv * 0.125f : -1e30f;
                s[j] = sv;
                tmax = fmaxf(tmax, sv);
            }
            float mn = fmaxf(mrun, tmax);
            if (mn > mrun) {
                float corr = __expf(mrun - mn);
                lrun *= corr;
                ull cp = pack2(corr, corr);
                #pragma unroll
                for (int d = 0; d < 8; d++) o2[d] = mul2(o2[d], cp);
                mrun = mn;
            }
            #pragma unroll
            for (int j = 0; j < KT; j++) {
                float p = __expf(s[j] - mrun);
                lrun += p;
                ull pp = pack2(p, p);
                const ulonglong2* vp = (const ulonglong2*)&Vs[j][sub * 16];
                #pragma unroll
                for (int i = 0; i < 4; i++) {
                    ulonglong2 v2 = vp[i];
                    fma2(o2[2 * i],     pp, v2.x);
                    fma2(o2[2 * i + 1], pp, v2.y);
                }
            }
        }
    }
    {
        const float inv = 1.f / lrun;
        ull ip = pack2(inv, inv);
        ulonglong2* op = (ulonglong2*)(Om + base + ((size_t)q << 10) + sub * 16);
        #pragma unroll
        for (int i = 0; i < 4; i++) {
            ulonglong2 t;
            t.x = mul2(o2[2 * i], ip);
            t.y = mul2(o2[2 * i + 1], ip);
            op[i] = t;
        }
    }
}

// ---------------- fused logits + softmax into d_out slice l ----------------
__global__ __launch_bounds__(256) void probs_kernel(const float* __restrict__ X,
                                                    const float* __restrict__ Wout,
                                                    float* __restrict__ out,
                                                    int l) {
    __shared__ float xs[8][1024];
    __shared__ float red[8][8];
    const int tid = threadIdx.x;
    const int row0 = blockIdx.x * 8;

    #pragma unroll
    for (int it = 0; it < 8; it++) {
        int idx = tid + it * 256;
        int m = idx >> 8;
        int c4 = idx & 255;
        int gr = row0 + m;
        float4 v = make_float4(0.f, 0.f, 0.f, 0.f);
        if (gr < M_ROWS) v = ((const float4*)&X[(size_t)gr * 1024])[c4];
        ((float4*)&xs[m][0])[c4] = v;
    }
    __syncthreads();

    float acc[8];
    #pragma unroll
    for (int m = 0; m < 8; m++) acc[m] = 0.f;
    const int v = tid;
    #pragma unroll 4
    for (int k0 = 0; k0 < 1024; k0 += 4) {
        float w0 = Wout[(k0 + 0) * VOCAB + v];
        float w1 = Wout[(k0 + 1) * VOCAB + v];
        float w2 = Wout[(k0 + 2) * VOCAB + v];
        float w3 = Wout[(k0 + 3) * VOCAB + v];
        #pragma unroll
        for (int m = 0; m < 8; m++) {
            float4 x4 = *(const float4*)&xs[m][k0];
            float t0 = fmaf(x4.x, w0, acc[m]);
            float t1 = fmaf(x4.y, w1, t0);
            float t2 = fmaf(x4.z, w2, t1);
            acc[m]   = fmaf(x4.w, w3, t2);
        }
    }

    const int lane = tid & 31;
    const int wid  = tid >> 5;
    float bmax[8];
    #pragma unroll
    for (int m = 0; m < 8; m++) {
        float x = acc[m];
        #pragma unroll
        for (int off = 16; off; off >>= 1)
            x = fmaxf(x, __shfl_xor_sync(0xffffffffu, x, off));
        if (lane == 0) red[m][wid] = x;
    }
    __syncthreads();
    #pragma unroll
    for (int m = 0; m < 8; m++) {
        float mx = red[m][0];
        #pragma unroll
        for (int w = 1; w < 8; w++) mx = fmaxf(mx, red[m][w]);
        bmax[m] = mx;
    }
    __syncthreads();
    float p[8];
    #pragma unroll
    for (int m = 0; m < 8; m++) {
        p[m] = __expf(acc[m] - bmax[m]);
        float x = p[m];
        #pragma unroll
        for (int off = 16; off; off >>= 1)
            x += __shfl_xor_sync(0xffffffffu, x, off);
        if (lane == 0) red[m][wid] = x;
    }
    __syncthreads();
    #pragma unroll
    for (int m = 0; m < 8; m++) {
        float sm = 0.f;
        #pragma unroll
        for (int w = 0; w < 8; w++) sm += red[m][w];
        int gr = row0 + m;
        if (gr < M_ROWS) {
            int b = gr / N_CTX;
            int t = gr - b * N_CTX;
            out[(((size_t)l * B_SZ + b) * N_CTX + t) * VOCAB + v] = p[m] / sm;
        }
    }
}

// ---------------- orchestration ----------------
extern "C" void kernel_launch(void* const* d_in, const int* in_sizes, int n_in,
                              void* d_out, int out_size) {
    const int*   ids  = (const int*)d_in[0];
    const float* emb  = (const float*)d_in[1];
    const float* Wq   = (const float*)d_in[2];
    const float* Wk   = (const float*)d_in[3];
    const float* Wv   = (const float*)d_in[4];
    const float* Wo   = (const float*)d_in[5];
    const float* Wout = (const float*)d_in[6];
    float* out = (float*)d_out;

    float *X, *Q, *K, *V, *O;
    __nv_bfloat16 *Xb, *Ob, *Wtq, *Wtk, *Wtv, *Wto;
    cudaGetSymbolAddress((void**)&X, g_X);
    cudaGetSymbolAddress((void**)&Q, g_Q);
    cudaGetSymbolAddress((void**)&K, g_K);
    cudaGetSymbolAddress((void**)&V, g_V);
    cudaGetSymbolAddress((void**)&O, g_O);
    cudaGetSymbolAddress((void**)&Xb, g_Xb);
    cudaGetSymbolAddress((void**)&Ob, g_Ob);
    cudaGetSymbolAddress((void**)&Wtq, g_Wtq);
    cudaGetSymbolAddress((void**)&Wtk, g_Wtk);
    cudaGetSymbolAddress((void**)&Wtv, g_Wtv);
    cudaGetSymbolAddress((void**)&Wto, g_Wto);

    // weight transpose + bf16 convert (all layers)
    dim3 wtg(32, 32, N_LAYERS), wtb(32, 8);
    wtrans_kernel<<<wtg, wtb>>>(Wq, Wtq);
    wtrans_kernel<<<wtg, wtb>>>(Wk, Wtk);
    wtrans_kernel<<<wtg, wtb>>>(Wv, Wtv);
    wtrans_kernel<<<wtg, wtb>>>(Wo, Wto);

    embed_kernel<<<(M_ROWS * D_MODEL + 255) / 256, 256>>>(ids, emb);
    probs_kernel<<<(M_ROWS + 7) / 8, 256>>>(X, Wout, out, 0);

    const int nconv = (M_ROWS * D_MODEL / 4 + 255) / 256;
    dim3 ggrid(8, (M_ROWS + 127) / 128);
    dim3 agrid((N_CTX + QT - 1) / QT, N_HEADS, B_SZ);
    for (int l = 0; l < N_LAYERS; l++) {
        const size_t woff = (size_t)l * D_MODEL * D_MODEL;
        conv_kernel<<<nconv, 256>>>(X, Xb);
        gemm_bf16<<<ggrid, 256>>>(Xb, Wtq + woff, nullptr, Q);
        gemm_bf16<<<ggrid, 256>>>(Xb, Wtk + woff, nullptr, K);
        gemm_bf16<<<ggrid, 256>>>(Xb, Wtv + woff, nullptr, V);
        attn_kernel<<<agrid, 256>>>(Q, K, V, O);
        conv_kernel<<<nconv, 256>>>(O, Ob);
        gemm_bf16<<<ggrid, 256>>>(Ob, Wto + woff, X, X);   // X += O @ Wo
        probs_kernel<<<(M_ROWS + 7) / 8, 256>>>(X, Wout, out, l + 1);
    }
}